// round 16
// baseline (speedup 1.0000x reference)
#include <cuda_runtime.h>
#include <math.h>

#define NG    4096
#define IW    96
#define IH    96
#define NPIX  (IW*IH)
#define NTILE 36            // 6x6 tiles of 16x16
#define RCH   32            // depth chunks for render parallelism
#define RCHSZ (NG/RCH)      // 128
#define TANFOV 0.36502849177392513f
#define LIMV   (1.3f*TANFOV)
#define FXY    (96.0f/(2.0f*TANFOV))
#define INV255 0.0039215686274509803f

typedef unsigned long long u64;

// ---------------- scratch (no allocations allowed) ----------------
__device__ float4 g_p0[NG], g_p1[NG], g_p3[NG];   // unsorted packed params (+bbox)
__device__ float2 g_p2[NG];
__device__ u64    g_key[NG];
__device__ int    g_tilecnt[NTILE];
__device__ unsigned int g_tilemask[NTILE];
__device__ float4 g_s0[NG], g_s1[NG], g_s3[NG];   // sorted
__device__ float2 g_s2[NG];
__device__ float4 g_partial4[RCH * NTILE * 256];  // packed (r,g,b,T)

// ---------------- 1) per-gaussian preprocess (vectorized loads) ----------------
__global__
void preprocess_kernel(const float* __restrict__ means,
                       const float* __restrict__ scales_raw,
                       const float4* __restrict__ rots4,
                       const float* __restrict__ op_raw,
                       const float4* __restrict__ shs4,
                       const float* __restrict__ view,
                       const float* __restrict__ proj,
                       const float* __restrict__ campos)
{
    int n = blockIdx.x * 32 + threadIdx.x;
    if (n >= NG) return;

    if (n < NTILE) { g_tilecnt[n] = 0; g_tilemask[n] = 0u; }   // per-replay reset

    float4 q4 = rots4[n];
    float sh[48];
    {
        const float4* sb = shs4 + n * 12;
        #pragma unroll
        for (int i = 0; i < 12; i++) {
            float4 v4 = sb[i];
            sh[4*i+0] = v4.x; sh[4*i+1] = v4.y; sh[4*i+2] = v4.z; sh[4*i+3] = v4.w;
        }
    }
    float mx = __ldg(means + 3*n + 0), my = __ldg(means + 3*n + 1), mz = __ldg(means + 3*n + 2);
    float sx = __expf(__ldg(scales_raw + 3*n + 0));
    float sy = __expf(__ldg(scales_raw + 3*n + 1));
    float sz = __expf(__ldg(scales_raw + 3*n + 2));
    float opr = __ldg(op_raw + n);

    float qr = q4.x, qx = q4.y, qy = q4.z, qz = q4.w;
    float qn = rsqrtf(qr*qr + qx*qx + qy*qy + qz*qz);
    qr *= qn; qx *= qn; qy *= qn; qz *= qn;

    float R00 = 1.f - 2.f*(qy*qy + qz*qz);
    float R01 = 2.f*(qx*qy - qr*qz);
    float R02 = 2.f*(qx*qz + qr*qy);
    float R10 = 2.f*(qx*qy + qr*qz);
    float R11 = 1.f - 2.f*(qx*qx + qz*qz);
    float R12 = 2.f*(qy*qz - qr*qx);
    float R20 = 2.f*(qx*qz - qr*qy);
    float R21 = 2.f*(qy*qz + qr*qx);
    float R22 = 1.f - 2.f*(qx*qx + qy*qy);

    float L00 = R00*sx, L01 = R01*sy, L02 = R02*sz;
    float L10 = R10*sx, L11 = R11*sy, L12 = R12*sz;
    float L20 = R20*sx, L21 = R21*sy, L22 = R22*sz;
    float S00 = L00*L00 + L01*L01 + L02*L02;
    float S01 = L00*L10 + L01*L11 + L02*L12;
    float S02 = L00*L20 + L01*L21 + L02*L22;
    float S11 = L10*L10 + L11*L11 + L12*L12;
    float S12 = L10*L20 + L11*L21 + L12*L22;
    float S22 = L20*L20 + L21*L21 + L22*L22;

    float v[16], p[16];
    #pragma unroll
    for (int i = 0; i < 16; i++) { v[i] = view[i]; p[i] = proj[i]; }

    float pv0 = v[0]*mx + v[1]*my + v[2]*mz + v[3];
    float pv1 = v[4]*mx + v[5]*my + v[6]*mz + v[7];
    float pv2 = v[8]*mx + v[9]*my + v[10]*mz + v[11];
    float depth = pv2;

    float ph0 = p[0]*mx + p[1]*my + p[2]*mz + p[3];
    float ph1 = p[4]*mx + p[5]*my + p[6]*mz + p[7];
    float ph3 = p[12]*mx + p[13]*my + p[14]*mz + p[15];
    float pw  = 1.f / (ph3 + 1e-7f);
    float mxs = ((ph0*pw + 1.f) * (float)IW - 1.f) * 0.5f;
    float mys = ((ph1*pw + 1.f) * (float)IH - 1.f) * 0.5f;

    float tz = depth;
    float invtz = 1.f / tz;
    float txc = fminf(fmaxf(pv0*invtz, -LIMV), LIMV) * tz;
    float tyc = fminf(fmaxf(pv1*invtz, -LIMV), LIMV) * tz;
    float J00 = FXY * invtz;
    float J02 = -FXY * txc * invtz * invtz;
    float J11 = FXY * invtz;
    float J12 = -FXY * tyc * invtz * invtz;

    float M00 = J00*v[0] + J02*v[8];
    float M01 = J00*v[1] + J02*v[9];
    float M02 = J00*v[2] + J02*v[10];
    float M10 = J11*v[4] + J12*v[8];
    float M11 = J11*v[5] + J12*v[9];
    float M12 = J11*v[6] + J12*v[10];

    float t00 = M00*S00 + M01*S01 + M02*S02;
    float t01 = M00*S01 + M01*S11 + M02*S12;
    float t02 = M00*S02 + M01*S12 + M02*S22;
    float t10 = M10*S00 + M11*S01 + M12*S02;
    float t11 = M10*S01 + M11*S11 + M12*S12;
    float t12 = M10*S02 + M11*S12 + M12*S22;
    float cov00 = t00*M00 + t01*M01 + t02*M02;
    float cov01 = t00*M10 + t01*M11 + t02*M12;
    float cov11 = t10*M10 + t11*M11 + t12*M12;

    float a  = cov00 + 0.3f;
    float bb = cov01;
    float c  = cov11 + 0.3f;
    float det = a*c - bb*bb;

    float op = 1.f / (1.f + __expf(-opr));

    float dx0 = mx - campos[0], dy0 = my - campos[1], dz0 = mz - campos[2];
    float rn = rsqrtf(dx0*dx0 + dy0*dy0 + dz0*dz0);
    float x = dx0*rn, y = dy0*rn, z = dz0*rn;
    float xx = x*x, yy = y*y, zz = z*z;
    float xy = x*y, yz = y*z, xz = x*z;

    const float C0f = 0.28209479177387814f;
    const float C1f = 0.4886025119029199f;
    const float C2f0 = 1.0925484305920792f, C2f1 = -1.0925484305920792f;
    const float C2f2 = 0.31539156525252005f, C2f3 = -1.0925484305920792f;
    const float C2f4 = 0.5462742152960396f;
    const float C3f0 = -0.5900435899266435f, C3f1 = 2.890611442640554f;
    const float C3f2 = -0.4570457994644658f, C3f3 = 0.3731763325901154f;
    const float C3f4 = -0.4570457994644658f, C3f5 = 1.445305721320277f;
    const float C3f6 = -0.5900435899266435f;

    float b1 = -C1f*y, b2 = C1f*z, b3 = -C1f*x;
    float b4 = C2f0*xy, b5 = C2f1*yz, b6 = C2f2*(2.f*zz - xx - yy);
    float b7 = C2f3*xz, b8 = C2f4*(xx - yy);
    float b9  = C3f0*y*(3.f*xx - yy);
    float b10 = C3f1*xy*z;
    float b11 = C3f2*y*(4.f*zz - xx - yy);
    float b12 = C3f3*z*(2.f*zz - 3.f*xx - 3.f*yy);
    float b13 = C3f4*x*(4.f*zz - xx - yy);
    float b14 = C3f5*z*(xx - yy);
    float b15 = C3f6*x*(xx - 3.f*yy);

    float col[3];
    #pragma unroll
    for (int ch = 0; ch < 3; ch++) {
        float res = C0f*sh[0+ch]
                  + b1*sh[3+ch]  + b2*sh[6+ch]  + b3*sh[9+ch]
                  + b4*sh[12+ch] + b5*sh[15+ch] + b6*sh[18+ch]
                  + b7*sh[21+ch] + b8*sh[24+ch]
                  + b9*sh[27+ch] + b10*sh[30+ch] + b11*sh[33+ch]
                  + b12*sh[36+ch] + b13*sh[39+ch] + b14*sh[42+ch] + b15*sh[45+ch];
        col[ch] = fmaxf(res + 0.5f, 0.f);
    }

    bool valid = (depth > 0.2f) && (det > 0.f);
    float A, B, C, pth;
    float bxmin = 1e9f, bxmax = -1e9f, bymin = 1e9f, bymax = -1e9f;
    float q2 = __logf(255.f * op) + 0.02f;
    if (valid && q2 > 0.f) {
        float invdet = 1.f / det;
        A = c * invdet;
        B = -bb * invdet;
        C = a * invdet;
        pth = -q2;
        float dxm = sqrtf(2.f * q2 * a) + 1e-3f;
        float dym = sqrtf(2.f * q2 * c) + 1e-3f;
        bxmin = mxs - dxm; bxmax = mxs + dxm;
        bymin = mys - dym; bymax = mys + dym;
    } else {
        mxs = 0.f; mys = 0.f;
        A = 0.f; B = 0.f; C = 0.f;
        op = 0.f;
        pth = 1.0f;
    }

    g_p0[n] = make_float4(mxs, mys, A, B);
    g_p1[n] = make_float4(C, op, col[0], col[1]);
    g_p2[n] = make_float2(col[2], pth);
    g_p3[n] = make_float4(bxmin, bxmax, bymin, bymax);

    unsigned int b32 = __float_as_uint(depth);
    b32 ^= (b32 >> 31) ? 0xFFFFFFFFu : 0x80000000u;
    g_key[n] = ((u64)b32 << 32) | (unsigned int)n;
}

// ---------------- 2) fused rank sort + scatter (bank-conflict-free, padded) ----------------
#define SLICE_PAD 257
__global__ __launch_bounds__(256)
void rank_scatter_kernel()
{
    __shared__ u64 keys[8 * SLICE_PAD];   // ~16.1 KB
    int t = threadIdx.x;
    int blk = blockIdx.x;
    int elem  = blk * 32 + (t >> 3);
    int slice = t & 7;
    u64 myk = g_key[elem];
    int cnt = 0;
    #pragma unroll
    for (int st = 0; st < 2; st++) {
        #pragma unroll
        for (int u = 0; u < 8; u++)
            keys[u * SLICE_PAD + t] = g_key[st*2048 + u*256 + t];
        __syncthreads();
        int kb = slice * SLICE_PAD;
        #pragma unroll 8
        for (int j = 0; j < 256; j++)
            cnt += (keys[kb + j] < myk) ? 1 : 0;
        __syncthreads();
    }
    cnt += __shfl_xor_sync(0xffffffffu, cnt, 1);
    cnt += __shfl_xor_sync(0xffffffffu, cnt, 2);
    cnt += __shfl_xor_sync(0xffffffffu, cnt, 4);
    if (slice == 0) {
        g_s0[cnt] = g_p0[elem];
        g_s1[cnt] = g_p1[elem];
        g_s2[cnt] = g_p2[elem];
        g_s3[cnt] = g_p3[elem];
    }
}

// ---------------- 3) tiled render: packed partials + empty-chunk skip ----------------
__global__ __launch_bounds__(256)
void render_tile_kernel(const float* __restrict__ bg, float* __restrict__ out)
{
    __shared__ float4 c0[RCHSZ];
    __shared__ float4 c1[RCHSZ];
    __shared__ float2 c2[RCHSZ];
    __shared__ int wcnt[4];
    __shared__ int sdone;

    int tile  = blockIdx.x;
    int chunk = blockIdx.y;
    int t = threadIdx.x;
    int w = t >> 5, lane = t & 31;

    float tx0 = (float)((tile % 6) * 16);
    float ty0 = (float)((tile / 6) * 16);
    float tx1 = tx0 + 15.f;
    float ty1 = ty0 + 15.f;
    float px = tx0 + (float)(t & 15);
    float py = ty0 + (float)(t >> 4);

    float T = 1.f, cr = 0.f, cg = 0.f, cb = 0.f;

    // cull: first 128 threads test this chunk's 128 bboxes
    bool hit = false;
    int gi = chunk * RCHSZ + t;
    if (t < RCHSZ) {
        float4 bbx = g_s3[gi];
        hit = (bbx.x <= tx1) && (bbx.y >= tx0) && (bbx.z <= ty1) && (bbx.w >= ty0);
    }
    unsigned int bal = __ballot_sync(0xffffffffu, hit);
    if (lane == 0 && w < 4) wcnt[w] = __popc(bal);
    __syncthreads();

    int off = 0, m = 0;
    #pragma unroll
    for (int i = 0; i < 4; i++) {
        int cnt = wcnt[i];
        if (i < w) off += cnt;
        m += cnt;
    }

    if (m > 0) {
        if (hit) {
            int pos = off + __popc(bal & ((1u << lane) - 1u));
            c0[pos] = g_s0[gi];
            c1[pos] = g_s1[gi];
            c2[pos] = g_s2[gi];
        }
        __syncthreads();

        for (int i = 0; i < m; i++) {
            float4 a0 = c0[i];
            float2 a2 = c2[i];
            float dx = px - a0.x;
            float dy = py - a0.y;
            float4 a1 = c1[i];
            float power = -0.5f * (a0.z*dx*dx + a1.x*dy*dy) - a0.w*dx*dy;
            if (power < a2.y) continue;
            float alpha = fminf(0.99f, a1.y * __expf(power));
            if (alpha < INV255) continue;
            float wgt = alpha * T;
            cr = fmaf(wgt, a1.z, cr);
            cg = fmaf(wgt, a1.w, cg);
            cb = fmaf(wgt, a2.x, cb);
            T *= (1.f - alpha);
        }

        // store packed partial + flag this chunk
        g_partial4[chunk * (NTILE * 256) + tile * 256 + t] = make_float4(cr, cg, cb, T);
        if (t == 0) atomicOr(&g_tilemask[tile], 1u << chunk);
    }

    // last block per tile folds the non-empty chunks
    __threadfence();
    if (t == 0) sdone = atomicAdd(&g_tilecnt[tile], 1);
    __syncthreads();
    if (sdone == RCH - 1) {
        __threadfence();
        unsigned int mask = g_tilemask[tile];
        float Tt = 1.f, r = 0.f, g = 0.f, b = 0.f;
        while (mask) {
            int k = __ffs(mask) - 1;
            mask &= mask - 1;
            float4 pp = g_partial4[k * (NTILE * 256) + tile * 256 + t];
            r += Tt * pp.x;
            g += Tt * pp.y;
            b += Tt * pp.z;
            Tt *= pp.w;
        }
        int pix = ((tile / 6) * 16 + (t >> 4)) * IW + (tile % 6) * 16 + (t & 15);
        out[pix]          = r + Tt * bg[0];
        out[NPIX + pix]   = g + Tt * bg[1];
        out[2*NPIX + pix] = b + Tt * bg[2];
    }
}

extern "C" void kernel_launch(void* const* d_in, const int* in_sizes, int n_in,
                              void* d_out, int out_size)
{
    const float* means      = (const float*)d_in[0];
    const float* scales_raw = (const float*)d_in[1];
    const float* rots       = (const float*)d_in[2];
    const float* op_raw     = (const float*)d_in[3];
    const float* shs        = (const float*)d_in[4];
    const float* view       = (const float*)d_in[5];
    const float* proj       = (const float*)d_in[6];
    const float* campos     = (const float*)d_in[7];
    const float* bg         = (const float*)d_in[8];
    float* out = (float*)d_out;

    preprocess_kernel<<<128, 32>>>(means, scales_raw, (const float4*)rots, op_raw,
                                   (const float4*)shs, view, proj, campos);
    rank_scatter_kernel<<<128, 256>>>();
    render_tile_kernel<<<dim3(NTILE, RCH), 256>>>(bg, out);
}

// round 17
// speedup vs baseline: 1.2452x; 1.2452x over previous
#include <cuda_runtime.h>
#include <math.h>

#define NG    4096
#define IW    96
#define IH    96
#define NPIX  (IW*IH)
#define NTILE 36            // 6x6 tiles of 16x16
#define RCH   16            // depth chunks for render parallelism
#define RCHSZ (NG/RCH)      // 256
#define TANFOV 0.36502849177392513f
#define LIMV   (1.3f*TANFOV)
#define FXY    (96.0f/(2.0f*TANFOV))
#define INV255 0.0039215686274509803f

typedef unsigned long long u64;

// ---------------- scratch (no allocations allowed) ----------------
__device__ float4 g_p0[NG], g_p1[NG], g_p3[NG];   // unsorted packed params (+bbox)
__device__ float2 g_p2[NG];
__device__ u64    g_key[NG];
__device__ int    g_tilecnt[NTILE];
__device__ float4 g_s0[NG], g_s1[NG], g_s3[NG];   // sorted
__device__ float2 g_s2[NG];
__device__ float4 g_partial4[RCH * NTILE * 256];  // packed (r,g,b,T)

// ---------------- 1) per-gaussian preprocess (vectorized loads) ----------------
__global__
void preprocess_kernel(const float* __restrict__ means,
                       const float* __restrict__ scales_raw,
                       const float4* __restrict__ rots4,
                       const float* __restrict__ op_raw,
                       const float4* __restrict__ shs4,
                       const float* __restrict__ view,
                       const float* __restrict__ proj,
                       const float* __restrict__ campos)
{
    int n = blockIdx.x * 32 + threadIdx.x;
    if (n >= NG) return;

    if (n < NTILE) g_tilecnt[n] = 0;   // per-replay reset

    float4 q4 = rots4[n];
    float sh[48];
    {
        const float4* sb = shs4 + n * 12;
        #pragma unroll
        for (int i = 0; i < 12; i++) {
            float4 v4 = sb[i];
            sh[4*i+0] = v4.x; sh[4*i+1] = v4.y; sh[4*i+2] = v4.z; sh[4*i+3] = v4.w;
        }
    }
    float mx = __ldg(means + 3*n + 0), my = __ldg(means + 3*n + 1), mz = __ldg(means + 3*n + 2);
    float sx = __expf(__ldg(scales_raw + 3*n + 0));
    float sy = __expf(__ldg(scales_raw + 3*n + 1));
    float sz = __expf(__ldg(scales_raw + 3*n + 2));
    float opr = __ldg(op_raw + n);

    float qr = q4.x, qx = q4.y, qy = q4.z, qz = q4.w;
    float qn = rsqrtf(qr*qr + qx*qx + qy*qy + qz*qz);
    qr *= qn; qx *= qn; qy *= qn; qz *= qn;

    float R00 = 1.f - 2.f*(qy*qy + qz*qz);
    float R01 = 2.f*(qx*qy - qr*qz);
    float R02 = 2.f*(qx*qz + qr*qy);
    float R10 = 2.f*(qx*qy + qr*qz);
    float R11 = 1.f - 2.f*(qx*qx + qz*qz);
    float R12 = 2.f*(qy*qz - qr*qx);
    float R20 = 2.f*(qx*qz - qr*qy);
    float R21 = 2.f*(qy*qz + qr*qx);
    float R22 = 1.f - 2.f*(qx*qx + qy*qy);

    float L00 = R00*sx, L01 = R01*sy, L02 = R02*sz;
    float L10 = R10*sx, L11 = R11*sy, L12 = R12*sz;
    float L20 = R20*sx, L21 = R21*sy, L22 = R22*sz;
    float S00 = L00*L00 + L01*L01 + L02*L02;
    float S01 = L00*L10 + L01*L11 + L02*L12;
    float S02 = L00*L20 + L01*L21 + L02*L22;
    float S11 = L10*L10 + L11*L11 + L12*L12;
    float S12 = L10*L20 + L11*L21 + L12*L22;
    float S22 = L20*L20 + L21*L21 + L22*L22;

    float v[16], p[16];
    #pragma unroll
    for (int i = 0; i < 16; i++) { v[i] = view[i]; p[i] = proj[i]; }

    float pv0 = v[0]*mx + v[1]*my + v[2]*mz + v[3];
    float pv1 = v[4]*mx + v[5]*my + v[6]*mz + v[7];
    float pv2 = v[8]*mx + v[9]*my + v[10]*mz + v[11];
    float depth = pv2;

    float ph0 = p[0]*mx + p[1]*my + p[2]*mz + p[3];
    float ph1 = p[4]*mx + p[5]*my + p[6]*mz + p[7];
    float ph3 = p[12]*mx + p[13]*my + p[14]*mz + p[15];
    float pw  = 1.f / (ph3 + 1e-7f);
    float mxs = ((ph0*pw + 1.f) * (float)IW - 1.f) * 0.5f;
    float mys = ((ph1*pw + 1.f) * (float)IH - 1.f) * 0.5f;

    float tz = depth;
    float invtz = 1.f / tz;
    float txc = fminf(fmaxf(pv0*invtz, -LIMV), LIMV) * tz;
    float tyc = fminf(fmaxf(pv1*invtz, -LIMV), LIMV) * tz;
    float J00 = FXY * invtz;
    float J02 = -FXY * txc * invtz * invtz;
    float J11 = FXY * invtz;
    float J12 = -FXY * tyc * invtz * invtz;

    float M00 = J00*v[0] + J02*v[8];
    float M01 = J00*v[1] + J02*v[9];
    float M02 = J00*v[2] + J02*v[10];
    float M10 = J11*v[4] + J12*v[8];
    float M11 = J11*v[5] + J12*v[9];
    float M12 = J11*v[6] + J12*v[10];

    float t00 = M00*S00 + M01*S01 + M02*S02;
    float t01 = M00*S01 + M01*S11 + M02*S12;
    float t02 = M00*S02 + M01*S12 + M02*S22;
    float t10 = M10*S00 + M11*S01 + M12*S02;
    float t11 = M10*S01 + M11*S11 + M12*S12;
    float t12 = M10*S02 + M11*S12 + M12*S22;
    float cov00 = t00*M00 + t01*M01 + t02*M02;
    float cov01 = t00*M10 + t01*M11 + t02*M12;
    float cov11 = t10*M10 + t11*M11 + t12*M12;

    float a  = cov00 + 0.3f;
    float bb = cov01;
    float c  = cov11 + 0.3f;
    float det = a*c - bb*bb;

    float op = 1.f / (1.f + __expf(-opr));

    float dx0 = mx - campos[0], dy0 = my - campos[1], dz0 = mz - campos[2];
    float rn = rsqrtf(dx0*dx0 + dy0*dy0 + dz0*dz0);
    float x = dx0*rn, y = dy0*rn, z = dz0*rn;
    float xx = x*x, yy = y*y, zz = z*z;
    float xy = x*y, yz = y*z, xz = x*z;

    const float C0f = 0.28209479177387814f;
    const float C1f = 0.4886025119029199f;
    const float C2f0 = 1.0925484305920792f, C2f1 = -1.0925484305920792f;
    const float C2f2 = 0.31539156525252005f, C2f3 = -1.0925484305920792f;
    const float C2f4 = 0.5462742152960396f;
    const float C3f0 = -0.5900435899266435f, C3f1 = 2.890611442640554f;
    const float C3f2 = -0.4570457994644658f, C3f3 = 0.3731763325901154f;
    const float C3f4 = -0.4570457994644658f, C3f5 = 1.445305721320277f;
    const float C3f6 = -0.5900435899266435f;

    float b1 = -C1f*y, b2 = C1f*z, b3 = -C1f*x;
    float b4 = C2f0*xy, b5 = C2f1*yz, b6 = C2f2*(2.f*zz - xx - yy);
    float b7 = C2f3*xz, b8 = C2f4*(xx - yy);
    float b9  = C3f0*y*(3.f*xx - yy);
    float b10 = C3f1*xy*z;
    float b11 = C3f2*y*(4.f*zz - xx - yy);
    float b12 = C3f3*z*(2.f*zz - 3.f*xx - 3.f*yy);
    float b13 = C3f4*x*(4.f*zz - xx - yy);
    float b14 = C3f5*z*(xx - yy);
    float b15 = C3f6*x*(xx - 3.f*yy);

    float col[3];
    #pragma unroll
    for (int ch = 0; ch < 3; ch++) {
        float res = C0f*sh[0+ch]
                  + b1*sh[3+ch]  + b2*sh[6+ch]  + b3*sh[9+ch]
                  + b4*sh[12+ch] + b5*sh[15+ch] + b6*sh[18+ch]
                  + b7*sh[21+ch] + b8*sh[24+ch]
                  + b9*sh[27+ch] + b10*sh[30+ch] + b11*sh[33+ch]
                  + b12*sh[36+ch] + b13*sh[39+ch] + b14*sh[42+ch] + b15*sh[45+ch];
        col[ch] = fmaxf(res + 0.5f, 0.f);
    }

    bool valid = (depth > 0.2f) && (det > 0.f);
    float A, B, C, pth;
    float bxmin = 1e9f, bxmax = -1e9f, bymin = 1e9f, bymax = -1e9f;
    float q2 = __logf(255.f * op) + 0.02f;
    if (valid && q2 > 0.f) {
        float invdet = 1.f / det;
        A = c * invdet;
        B = -bb * invdet;
        C = a * invdet;
        pth = -q2;
        float dxm = sqrtf(2.f * q2 * a) + 1e-3f;
        float dym = sqrtf(2.f * q2 * c) + 1e-3f;
        bxmin = mxs - dxm; bxmax = mxs + dxm;
        bymin = mys - dym; bymax = mys + dym;
    } else {
        mxs = 0.f; mys = 0.f;
        A = 0.f; B = 0.f; C = 0.f;
        op = 0.f;
        pth = 1.0f;
    }

    g_p0[n] = make_float4(mxs, mys, A, B);
    g_p1[n] = make_float4(C, op, col[0], col[1]);
    g_p2[n] = make_float2(col[2], pth);
    g_p3[n] = make_float4(bxmin, bxmax, bymin, bymax);

    unsigned int b32 = __float_as_uint(depth);
    b32 ^= (b32 >> 31) ? 0xFFFFFFFFu : 0x80000000u;
    g_key[n] = ((u64)b32 << 32) | (unsigned int)n;
}

// ---------------- 2) fused rank sort + scatter (bank-conflict-free, padded) ----------------
#define SLICE_PAD 257
__global__ __launch_bounds__(256)
void rank_scatter_kernel()
{
    __shared__ u64 keys[8 * SLICE_PAD];   // ~16.1 KB
    int t = threadIdx.x;
    int blk = blockIdx.x;
    int elem  = blk * 32 + (t >> 3);
    int slice = t & 7;
    u64 myk = g_key[elem];
    int cnt = 0;
    #pragma unroll
    for (int st = 0; st < 2; st++) {
        #pragma unroll
        for (int u = 0; u < 8; u++)
            keys[u * SLICE_PAD + t] = g_key[st*2048 + u*256 + t];
        __syncthreads();
        int kb = slice * SLICE_PAD;
        #pragma unroll 8
        for (int j = 0; j < 256; j++)
            cnt += (keys[kb + j] < myk) ? 1 : 0;
        __syncthreads();
    }
    cnt += __shfl_xor_sync(0xffffffffu, cnt, 1);
    cnt += __shfl_xor_sync(0xffffffffu, cnt, 2);
    cnt += __shfl_xor_sync(0xffffffffu, cnt, 4);
    if (slice == 0) {
        g_s0[cnt] = g_p0[elem];
        g_s1[cnt] = g_p1[elem];
        g_s2[cnt] = g_p2[elem];
        g_s3[cnt] = g_p3[elem];
    }
}

// ---------------- 3) tiled render (RCH=16, single wave) + packed partials ----------------
__global__ __launch_bounds__(256)
void render_tile_kernel(const float* __restrict__ bg, float* __restrict__ out)
{
    __shared__ float4 c0[RCHSZ];
    __shared__ float4 c1[RCHSZ];
    __shared__ float2 c2[RCHSZ];
    __shared__ int wcnt[8];
    __shared__ int sdone;

    int tile  = blockIdx.x;
    int chunk = blockIdx.y;
    int t = threadIdx.x;
    int w = t >> 5, lane = t & 31;

    float tx0 = (float)((tile % 6) * 16);
    float ty0 = (float)((tile / 6) * 16);
    float tx1 = tx0 + 15.f;
    float ty1 = ty0 + 15.f;
    float px = tx0 + (float)(t & 15);
    float py = ty0 + (float)(t >> 4);

    float T = 1.f, cr = 0.f, cg = 0.f, cb = 0.f;

    // cull: all 256 threads test this chunk's 256 bboxes
    int gi = chunk * RCHSZ + t;
    float4 bbx = g_s3[gi];
    bool hit = (bbx.x <= tx1) && (bbx.y >= tx0) && (bbx.z <= ty1) && (bbx.w >= ty0);
    unsigned int bal = __ballot_sync(0xffffffffu, hit);
    if (lane == 0) wcnt[w] = __popc(bal);
    __syncthreads();

    int off = 0, m = 0;
    #pragma unroll
    for (int i = 0; i < 8; i++) {
        int cnt = wcnt[i];
        if (i < w) off += cnt;
        m += cnt;
    }
    if (hit) {
        int pos = off + __popc(bal & ((1u << lane) - 1u));
        c0[pos] = g_s0[gi];
        c1[pos] = g_s1[gi];
        c2[pos] = g_s2[gi];
    }
    __syncthreads();

    for (int i = 0; i < m; i++) {
        float4 a0 = c0[i];
        float2 a2 = c2[i];
        float dx = px - a0.x;
        float dy = py - a0.y;
        float4 a1 = c1[i];
        float power = -0.5f * (a0.z*dx*dx + a1.x*dy*dy) - a0.w*dx*dy;
        if (power < a2.y) continue;
        float alpha = fminf(0.99f, a1.y * __expf(power));
        if (alpha < INV255) continue;
        float wgt = alpha * T;
        cr = fmaf(wgt, a1.z, cr);
        cg = fmaf(wgt, a1.w, cg);
        cb = fmaf(wgt, a2.x, cb);
        T *= (1.f - alpha);
    }

    // packed partial: one STG.128 per thread
    g_partial4[chunk * (NTILE * 256) + tile * 256 + t] = make_float4(cr, cg, cb, T);

    // last block per tile folds the chunks (proven threadfence reduction)
    __threadfence();
    if (t == 0) sdone = atomicAdd(&g_tilecnt[tile], 1);
    __syncthreads();
    if (sdone == RCH - 1) {
        __threadfence();
        float Tt = 1.f, r = 0.f, g = 0.f, b = 0.f;
        #pragma unroll
        for (int k = 0; k < RCH; k++) {
            float4 pp = g_partial4[k * (NTILE * 256) + tile * 256 + t];
            r += Tt * pp.x;
            g += Tt * pp.y;
            b += Tt * pp.z;
            Tt *= pp.w;
        }
        int pix = ((tile / 6) * 16 + (t >> 4)) * IW + (tile % 6) * 16 + (t & 15);
        out[pix]          = r + Tt * bg[0];
        out[NPIX + pix]   = g + Tt * bg[1];
        out[2*NPIX + pix] = b + Tt * bg[2];
    }
}

extern "C" void kernel_launch(void* const* d_in, const int* in_sizes, int n_in,
                              void* d_out, int out_size)
{
    const float* means      = (const float*)d_in[0];
    const float* scales_raw = (const float*)d_in[1];
    const float* rots       = (const float*)d_in[2];
    const float* op_raw     = (const float*)d_in[3];
    const float* shs        = (const float*)d_in[4];
    const float* view       = (const float*)d_in[5];
    const float* proj       = (const float*)d_in[6];
    const float* campos     = (const float*)d_in[7];
    const float* bg         = (const float*)d_in[8];
    float* out = (float*)d_out;

    preprocess_kernel<<<128, 32>>>(means, scales_raw, (const float4*)rots, op_raw,
                                   (const float4*)shs, view, proj, campos);
    rank_scatter_kernel<<<128, 256>>>();
    render_tile_kernel<<<dim3(NTILE, RCH), 256>>>(bg, out);
}